// round 8
// baseline (speedup 1.0000x reference)
#include <cuda_runtime.h>
#include <math.h>

#define W_IMG 1024
#define N_PIX (W_IMG * W_IMG)
#define MAXB 8
#define NTH 256

typedef unsigned long long u64;

__device__ __forceinline__ u64 pk(float lo, float hi) {
    u64 r; asm("mov.b64 %0, {%1, %2};" : "=l"(r) : "f"(lo), "f"(hi)); return r;
}
__device__ __forceinline__ void upk(float& lo, float& hi, u64 v) {
    asm("mov.b64 {%0, %1}, %2;" : "=f"(lo), "=f"(hi) : "l"(v));
}
__device__ __forceinline__ u64 fma2(u64 a, u64 b, u64 c) {
    u64 r; asm("fma.rn.f32x2 %0, %1, %2, %3;" : "=l"(r) : "l"(a), "l"(b), "l"(c)); return r;
}
__device__ __forceinline__ u64 mul2(u64 a, u64 b) {
    u64 r; asm("mul.rn.f32x2 %0, %1, %2;" : "=l"(r) : "l"(a), "l"(b)); return r;
}

// per-block partial stats: [b][block (by*16+bx)][16]
// [0..2]=sum q_c^2, [3..5]=sum k_c^2, [6..14]=sum q_c*k_d
__device__ float g_part[MAXB][512][16];

// ---------------------------------------------------------------------------
// k_stats: 2-wide x 4-tall patch per thread, all math in packed f32x2.
// Block tile = 64 wide x 32 tall. K path first (kout pairs in registers),
// then Q path accumulating packed stats. Writes per-block partials.
// ---------------------------------------------------------------------------
__global__ __launch_bounds__(NTH) void k_stats(const float* __restrict__ x,
                                               const float* __restrict__ fhigh,
                                               const float* __restrict__ qC,
                                               const float* __restrict__ qD,
                                               const float* __restrict__ kC,
                                               const float* __restrict__ kD) {
    __shared__ float sred[NTH / 32][15];

    const int tid = threadIdx.x;
    const int b = blockIdx.z;
    const int warp = tid >> 5, lane = tid & 31;
    const int wx0 = blockIdx.x * 64;
    const int px0 = wx0 + lane * 2;
    const int y0 = blockIdx.y * 32 + warp * 4;

    const float* __restrict__ xb = x + (size_t)b * 3 * N_PIX;
    const float* __restrict__ fb = fhigh + (size_t)b * 3 * N_PIX;

    const bool is_e = (lane == 0) | (lane == 31);
    const int ex = (lane == 0) ? wx0 - 1 : wx0 + 64;
    const bool ex_ok = (unsigned)ex < (unsigned)W_IMG;

    u64 p2[15];
#pragma unroll
    for (int i = 0; i < 15; i++) p2[i] = 0ull;

    u64 kout2[3][4];  // [ch][row] packed pixel pair

    // ================= K path (input x, channels-last) =================
    {
        u64 cwb[9], dwb[27];
#pragma unroll
        for (int i = 0; i < 9; i++) { float w = kC[i]; cwb[i] = pk(w, w); }
#pragma unroll
        for (int i = 0; i < 27; i++) { float w = kD[i]; dwb[i] = pk(w, w); }

        u64 a0[3] = {0ull, 0ull, 0ull}, a1[3] = {0ull, 0ull, 0ull}, a2[3] = {0ull, 0ull, 0ull};

#pragma unroll
        for (int iy = 0; iy < 6; iy++) {
            const int yin = y0 + iy - 1;
            const bool yok = (unsigned)yin < (unsigned)W_IMG;

            u64 h2[3] = {0ull, 0ull, 0ull};
            if (yok) {
                const float* px = xb + (size_t)(yin * W_IMG + px0) * 3;
                float2 u0 = *(const float2*)px;
                float2 u1 = *(const float2*)(px + 2);
                float2 u2 = *(const float2*)(px + 4);
                // pixel0 = (u0.x,u0.y,u1.x), pixel1 = (u1.y,u2.x,u2.y)
                u64 g0 = pk(u0.x, u1.y);
                u64 g1 = pk(u0.y, u2.x);
                u64 g2 = pk(u1.x, u2.y);
#pragma unroll
                for (int c = 0; c < 3; c++)
                    h2[c] = fma2(cwb[c * 3 + 0], g0,
                            fma2(cwb[c * 3 + 1], g1,
                            mul2(cwb[c * 3 + 2], g2)));
            }
            float he[3] = {0.f, 0.f, 0.f};
            if (yok && is_e && ex_ok) {
                const float* pe = xb + (size_t)(yin * W_IMG + ex) * 3;
                float g0 = pe[0], g1 = pe[1], g2 = pe[2];
                float lo0, hi0, lo1, hi1, lo2, hi2;
                upk(lo0, hi0, cwb[0]); upk(lo1, hi1, cwb[1]); upk(lo2, hi2, cwb[2]);
                he[0] = lo0 * g0 + lo1 * g1 + lo2 * g2;
                upk(lo0, hi0, cwb[3]); upk(lo1, hi1, cwb[4]); upk(lo2, hi2, cwb[5]);
                he[1] = lo0 * g0 + lo1 * g1 + lo2 * g2;
                upk(lo0, hi0, cwb[6]); upk(lo1, hi1, cwb[7]); upk(lo2, hi2, cwb[8]);
                he[2] = lo0 * g0 + lo1 * g1 + lo2 * g2;
            }
#pragma unroll
            for (int c = 0; c < 3; c++) {
                float m0, m1;
                upk(m0, m1, h2[c]);
                float hl = __shfl_up_sync(0xffffffffu, m1, 1);
                float hr = __shfl_down_sync(0xffffffffu, m0, 1);
                if (lane == 0) hl = he[c];
                if (lane == 31) hr = he[c];
                u64 L = pk(hl, m0);
                u64 R = pk(m1, hr);
                u64 M = h2[c];
                a0[c] = fma2(dwb[c * 9 + 6], L, fma2(dwb[c * 9 + 7], M, fma2(dwb[c * 9 + 8], R, a0[c])));
                a1[c] = fma2(dwb[c * 9 + 3], L, fma2(dwb[c * 9 + 4], M, fma2(dwb[c * 9 + 5], R, a1[c])));
                a2[c] = fma2(dwb[c * 9 + 0], L, fma2(dwb[c * 9 + 1], M, fma2(dwb[c * 9 + 2], R, a2[c])));
            }
            if (iy >= 2) {
                const int r = iy - 2;
#pragma unroll
                for (int c = 0; c < 3; c++) {
                    kout2[c][r] = a0[c];
                    p2[3 + c] = fma2(a0[c], a0[c], p2[3 + c]);
                }
            }
#pragma unroll
            for (int c = 0; c < 3; c++) { a0[c] = a1[c]; a1[c] = a2[c]; a2[c] = 0ull; }
        }
    }

    // ================= Q path (input fhigh, planar) =================
    {
        u64 cwb[9], dwb[27];
#pragma unroll
        for (int i = 0; i < 9; i++) { float w = qC[i]; cwb[i] = pk(w, w); }
#pragma unroll
        for (int i = 0; i < 27; i++) { float w = qD[i]; dwb[i] = pk(w, w); }

        u64 a0[3] = {0ull, 0ull, 0ull}, a1[3] = {0ull, 0ull, 0ull}, a2[3] = {0ull, 0ull, 0ull};

#pragma unroll
        for (int iy = 0; iy < 6; iy++) {
            const int yin = y0 + iy - 1;
            const bool yok = (unsigned)yin < (unsigned)W_IMG;

            u64 h2[3] = {0ull, 0ull, 0ull};
            if (yok) {
                const size_t o = (size_t)yin * W_IMG + px0;
                float2 f0 = *(const float2*)(fb + o);
                float2 f1 = *(const float2*)(fb + o + N_PIX);
                float2 f2 = *(const float2*)(fb + o + 2 * N_PIX);
                u64 g0 = pk(f0.x, f0.y);
                u64 g1 = pk(f1.x, f1.y);
                u64 g2 = pk(f2.x, f2.y);
#pragma unroll
                for (int c = 0; c < 3; c++)
                    h2[c] = fma2(cwb[c * 3 + 0], g0,
                            fma2(cwb[c * 3 + 1], g1,
                            mul2(cwb[c * 3 + 2], g2)));
            }
            float he[3] = {0.f, 0.f, 0.f};
            if (yok && is_e && ex_ok) {
                const size_t o = (size_t)yin * W_IMG + ex;
                float g0 = fb[o], g1 = fb[o + N_PIX], g2 = fb[o + 2 * N_PIX];
                float lo0, hi0, lo1, hi1, lo2, hi2;
                upk(lo0, hi0, cwb[0]); upk(lo1, hi1, cwb[1]); upk(lo2, hi2, cwb[2]);
                he[0] = lo0 * g0 + lo1 * g1 + lo2 * g2;
                upk(lo0, hi0, cwb[3]); upk(lo1, hi1, cwb[4]); upk(lo2, hi2, cwb[5]);
                he[1] = lo0 * g0 + lo1 * g1 + lo2 * g2;
                upk(lo0, hi0, cwb[6]); upk(lo1, hi1, cwb[7]); upk(lo2, hi2, cwb[8]);
                he[2] = lo0 * g0 + lo1 * g1 + lo2 * g2;
            }
#pragma unroll
            for (int c = 0; c < 3; c++) {
                float m0, m1;
                upk(m0, m1, h2[c]);
                float hl = __shfl_up_sync(0xffffffffu, m1, 1);
                float hr = __shfl_down_sync(0xffffffffu, m0, 1);
                if (lane == 0) hl = he[c];
                if (lane == 31) hr = he[c];
                u64 L = pk(hl, m0);
                u64 R = pk(m1, hr);
                u64 M = h2[c];
                a0[c] = fma2(dwb[c * 9 + 6], L, fma2(dwb[c * 9 + 7], M, fma2(dwb[c * 9 + 8], R, a0[c])));
                a1[c] = fma2(dwb[c * 9 + 3], L, fma2(dwb[c * 9 + 4], M, fma2(dwb[c * 9 + 5], R, a1[c])));
                a2[c] = fma2(dwb[c * 9 + 0], L, fma2(dwb[c * 9 + 1], M, fma2(dwb[c * 9 + 2], R, a2[c])));
            }
            if (iy >= 2) {
                const int r = iy - 2;
#pragma unroll
                for (int c = 0; c < 3; c++) {
                    u64 q = a0[c];
                    p2[c] = fma2(q, q, p2[c]);
#pragma unroll
                    for (int d = 0; d < 3; d++)
                        p2[6 + c * 3 + d] = fma2(q, kout2[d][r], p2[6 + c * 3 + d]);
                }
            }
#pragma unroll
            for (int c = 0; c < 3; c++) { a0[c] = a1[c]; a1[c] = a2[c]; a2[c] = 0ull; }
        }
    }

    // collapse pairs -> scalar, then reduce
    float p[15];
#pragma unroll
    for (int i = 0; i < 15; i++) {
        float lo, hi;
        upk(lo, hi, p2[i]);
        p[i] = lo + hi;
    }
#pragma unroll
    for (int i = 0; i < 15; i++)
#pragma unroll
        for (int o = 16; o; o >>= 1)
            p[i] += __shfl_down_sync(0xffffffffu, p[i], o);
    if (lane == 0) {
#pragma unroll
        for (int i = 0; i < 15; i++) sred[warp][i] = p[i];
    }
    __syncthreads();
    if (tid < 15) {
        float t = 0.f;
#pragma unroll
        for (int w2 = 0; w2 < NTH / 32; w2++) t += sred[w2][tid];
        g_part[b][blockIdx.y * 16 + blockIdx.x][tid] = t;
    }
}

// ---------------------------------------------------------------------------
// k_out: prologue reduces 512 partials -> stats -> M; body = 4x8 patch
// k-conv + 3x3 map (proven R7 scalar version).
// ---------------------------------------------------------------------------
__global__ __launch_bounds__(NTH) void k_out(const float* __restrict__ x,
                                             const float* __restrict__ kC,
                                             const float* __restrict__ kD,
                                             const float* __restrict__ proj_w,
                                             const float* __restrict__ proj_b,
                                             const float* __restrict__ temp,
                                             float* __restrict__ out) {
    __shared__ float sM[9];
    __shared__ float sred[NTH / 32][15];
    __shared__ float sstat[15];

    const int tid = threadIdx.x;
    const int b = blockIdx.z;
    const int warp = tid >> 5, lane = tid & 31;

    // --- prologue: reduce 512 partials x 15, then compute M ---
    {
        float p[15];
        const float4* rowA = (const float4*)g_part[b][tid];
        const float4* rowB = (const float4*)g_part[b][tid + 256];
        float4 a0 = rowA[0], a1 = rowA[1], a2 = rowA[2], a3 = rowA[3];
        float4 b0v = rowB[0], b1v = rowB[1], b2v = rowB[2], b3v = rowB[3];
        p[0] = a0.x + b0v.x;  p[1] = a0.y + b0v.y;  p[2] = a0.z + b0v.z;  p[3] = a0.w + b0v.w;
        p[4] = a1.x + b1v.x;  p[5] = a1.y + b1v.y;  p[6] = a1.z + b1v.z;  p[7] = a1.w + b1v.w;
        p[8] = a2.x + b2v.x;  p[9] = a2.y + b2v.y;  p[10] = a2.z + b2v.z; p[11] = a2.w + b2v.w;
        p[12] = a3.x + b3v.x; p[13] = a3.y + b3v.y; p[14] = a3.z + b3v.z;
#pragma unroll
        for (int i = 0; i < 15; i++)
#pragma unroll
            for (int o = 16; o; o >>= 1)
                p[i] += __shfl_down_sync(0xffffffffu, p[i], o);
        if (lane == 0) {
#pragma unroll
            for (int i = 0; i < 15; i++) sred[warp][i] = p[i];
        }
        __syncthreads();
        if (tid < 15) {
            float t = 0.f;
#pragma unroll
            for (int w2 = 0; w2 < NTH / 32; w2++) t += sred[w2][tid];
            sstat[tid] = t;
        }
        __syncthreads();
        if (tid == 0) {
            float T = temp[0];
            float nq[3], nk[3];
#pragma unroll
            for (int c = 0; c < 3; c++) {
                nq[c] = fmaxf(sqrtf(sstat[c]), 1e-12f);
                nk[c] = fmaxf(sqrtf(sstat[3 + c]), 1e-12f);
            }
            float a[3][3];
#pragma unroll
            for (int c = 0; c < 3; c++)
#pragma unroll
                for (int d = 0; d < 3; d++)
                    a[c][d] = sstat[6 + c * 3 + d] / (nq[c] * nk[d]) * T;
#pragma unroll
            for (int c = 0; c < 3; c++) {
                float mx = fmaxf(a[c][0], fmaxf(a[c][1], a[c][2]));
                float e0 = expf(a[c][0] - mx);
                float e1 = expf(a[c][1] - mx);
                float e2 = expf(a[c][2] - mx);
                float inv = 1.f / (e0 + e1 + e2);
                a[c][0] = e0 * inv; a[c][1] = e1 * inv; a[c][2] = e2 * inv;
            }
#pragma unroll
            for (int co = 0; co < 3; co++)
#pragma unroll
                for (int d = 0; d < 3; d++) {
                    float mm = 0.f;
#pragma unroll
                    for (int c = 0; c < 3; c++) mm += proj_w[co * 3 + c] * a[c][d];
                    sM[co * 3 + d] = mm;
                }
        }
        __syncthreads();
    }

    const int wx0 = blockIdx.x * 128;
    const int px0 = wx0 + lane * 4;
    const int y0 = blockIdx.y * 64 + warp * 8;

    const float* __restrict__ xb = x + (size_t)b * 3 * N_PIX;

    const bool is_e = (lane == 0) | (lane == 31);
    const int ex = (lane == 0) ? wx0 - 1 : wx0 + 128;
    const bool ex_ok = (unsigned)ex < (unsigned)W_IMG;

    float cw[9], dw[27];
#pragma unroll
    for (int i = 0; i < 9; i++) cw[i] = kC[i];
#pragma unroll
    for (int i = 0; i < 27; i++) dw[i] = kD[i];

    float m[9];
#pragma unroll
    for (int i = 0; i < 9; i++) m[i] = sM[i];
    const float b0 = proj_b[0], b1 = proj_b[1], b2 = proj_b[2];

    float a0[3][4], a1[3][4], a2[3][4];
#pragma unroll
    for (int c = 0; c < 3; c++)
#pragma unroll
        for (int j = 0; j < 4; j++) { a0[c][j] = a1[c][j] = a2[c][j] = 0.f; }

#pragma unroll
    for (int iy = 0; iy < 10; iy++) {
        const int yin = y0 + iy - 1;
        const bool yok = (unsigned)yin < (unsigned)W_IMG;

        float hm[3][4];
#pragma unroll
        for (int c = 0; c < 3; c++)
#pragma unroll
            for (int j = 0; j < 4; j++) hm[c][j] = 0.f;

        if (yok) {
            const float4* p4 = (const float4*)(xb + (size_t)(yin * W_IMG + px0) * 3);
            float4 v0 = p4[0], v1 = p4[1], v2 = p4[2];
            float g[4][3] = {{v0.x, v0.y, v0.z}, {v0.w, v1.x, v1.y},
                             {v1.z, v1.w, v2.x}, {v2.y, v2.z, v2.w}};
#pragma unroll
            for (int j = 0; j < 4; j++)
#pragma unroll
                for (int c = 0; c < 3; c++)
                    hm[c][j] = cw[c * 3] * g[j][0] + cw[c * 3 + 1] * g[j][1] + cw[c * 3 + 2] * g[j][2];
        }
        float he[3] = {0.f, 0.f, 0.f};
        if (yok && is_e && ex_ok) {
            const float* pe = xb + (size_t)(yin * W_IMG + ex) * 3;
            float g0 = pe[0], g1 = pe[1], g2 = pe[2];
#pragma unroll
            for (int c = 0; c < 3; c++)
                he[c] = cw[c * 3] * g0 + cw[c * 3 + 1] * g1 + cw[c * 3 + 2] * g2;
        }
        float hl[3], hr[3];
#pragma unroll
        for (int c = 0; c < 3; c++) {
            hl[c] = __shfl_up_sync(0xffffffffu, hm[c][3], 1);
            hr[c] = __shfl_down_sync(0xffffffffu, hm[c][0], 1);
            if (lane == 0) hl[c] = he[c];
            if (lane == 31) hr[c] = he[c];
        }
#pragma unroll
        for (int c = 0; c < 3; c++)
#pragma unroll
            for (int j = 0; j < 4; j++) {
                float L = j ? hm[c][j - 1] : hl[c];
                float M_ = hm[c][j];
                float R = (j < 3) ? hm[c][j + 1] : hr[c];
                a0[c][j] += dw[c * 9 + 6] * L + dw[c * 9 + 7] * M_ + dw[c * 9 + 8] * R;
                a1[c][j] += dw[c * 9 + 3] * L + dw[c * 9 + 4] * M_ + dw[c * 9 + 5] * R;
                a2[c][j] += dw[c * 9 + 0] * L + dw[c * 9 + 1] * M_ + dw[c * 9 + 2] * R;
            }
        if (iy >= 2) {
            const int yout = y0 + iy - 2;
            float o[12];
#pragma unroll
            for (int j = 0; j < 4; j++) {
                float k0 = a0[0][j], k1 = a0[1][j], k2 = a0[2][j];
                o[j * 3 + 0] = m[0] * k0 + m[1] * k1 + m[2] * k2 + b0;
                o[j * 3 + 1] = m[3] * k0 + m[4] * k1 + m[5] * k2 + b1;
                o[j * 3 + 2] = m[6] * k0 + m[7] * k1 + m[8] * k2 + b2;
            }
            float4* q4 = (float4*)(out + ((size_t)b * N_PIX + (size_t)yout * W_IMG + px0) * 3);
            q4[0] = make_float4(o[0], o[1], o[2], o[3]);
            q4[1] = make_float4(o[4], o[5], o[6], o[7]);
            q4[2] = make_float4(o[8], o[9], o[10], o[11]);
        }
#pragma unroll
        for (int c = 0; c < 3; c++)
#pragma unroll
            for (int j = 0; j < 4; j++) {
                a0[c][j] = a1[c][j];
                a1[c][j] = a2[c][j];
                a2[c][j] = 0.f;
            }
    }
}

extern "C" void kernel_launch(void* const* d_in, const int* in_sizes, int n_in,
                              void* d_out, int out_size) {
    const float* x     = (const float*)d_in[0];
    const float* fhigh = (const float*)d_in[1];
    const float* qCw   = (const float*)d_in[2];
    const float* qdw   = (const float*)d_in[3];
    const float* kCw   = (const float*)d_in[4];
    const float* kdw   = (const float*)d_in[5];
    const float* projw = (const float*)d_in[6];
    const float* projb = (const float*)d_in[7];
    const float* temp  = (const float*)d_in[8];
    float* out = (float*)d_out;

    int B = in_sizes[0] / (N_PIX * 3);
    if (B > MAXB) B = MAXB;

    dim3 gridS(W_IMG / 64, W_IMG / 32, B);   // 16 x 32 = 512 blocks per batch
    k_stats<<<gridS, NTH>>>(x, fhigh, qCw, qdw, kCw, kdw);
    dim3 gridO(W_IMG / 128, W_IMG / 64, B);
    k_out<<<gridO, NTH>>>(x, kCw, kdw, projw, projb, temp, out);
}

// round 9
// speedup vs baseline: 2.4998x; 2.4998x over previous
#include <cuda_runtime.h>
#include <math.h>

#define W_IMG 1024
#define N_PIX (W_IMG * W_IMG)
#define MAXB 8
#define NTH 256

// per-block partial stats: [b][block (by*8+bx)][16]
// [0..2]=sum q_c^2, [3..5]=sum k_c^2, [6..14]=sum q_c*k_d
__device__ float g_part[MAXB][256][16];

// ---------------------------------------------------------------------------
// k_stats: 4x4 patch per thread (register kout). K path first, then Q path
// accumulating the 15 per-batch statistics. Writes per-block partials.
// ---------------------------------------------------------------------------
__global__ __launch_bounds__(NTH, 2) void k_stats(const float* __restrict__ x,
                                                  const float* __restrict__ fhigh,
                                                  const float* __restrict__ qC,
                                                  const float* __restrict__ qD,
                                                  const float* __restrict__ kC,
                                                  const float* __restrict__ kD) {
    __shared__ float red[NTH / 32][15];

    const int tid = threadIdx.x;
    const int b = blockIdx.z;
    const int warp = tid >> 5, lane = tid & 31;
    const int wx0 = blockIdx.x * 128;
    const int px0 = wx0 + lane * 4;
    const int y0 = blockIdx.y * 32 + warp * 4;

    const float* __restrict__ xb = x + (size_t)b * 3 * N_PIX;
    const float* __restrict__ fb = fhigh + (size_t)b * 3 * N_PIX;

    const bool is_e = (lane == 0) | (lane == 31);
    const int ex = (lane == 0) ? wx0 - 1 : wx0 + 128;
    const bool ex_ok = (unsigned)ex < (unsigned)W_IMG;

    float p[15];
#pragma unroll
    for (int i = 0; i < 15; i++) p[i] = 0.f;

    float kout[3][4][4];  // [ch][row][j]

    // ================= K path (input x, channels-last) =================
    {
        float cw[9], dw[27];
#pragma unroll
        for (int i = 0; i < 9; i++) cw[i] = kC[i];
#pragma unroll
        for (int i = 0; i < 27; i++) dw[i] = kD[i];

        float a0[3][4], a1[3][4], a2[3][4];
#pragma unroll
        for (int c = 0; c < 3; c++)
#pragma unroll
            for (int j = 0; j < 4; j++) { a0[c][j] = a1[c][j] = a2[c][j] = 0.f; }

#pragma unroll
        for (int iy = 0; iy < 6; iy++) {
            const int yin = y0 + iy - 1;
            const bool yok = (unsigned)yin < (unsigned)W_IMG;

            float hm[3][4];
#pragma unroll
            for (int c = 0; c < 3; c++)
#pragma unroll
                for (int j = 0; j < 4; j++) hm[c][j] = 0.f;

            if (yok) {
                const float4* p4 = (const float4*)(xb + (size_t)(yin * W_IMG + px0) * 3);
                float4 v0 = p4[0], v1 = p4[1], v2 = p4[2];
                float g[4][3] = {{v0.x, v0.y, v0.z}, {v0.w, v1.x, v1.y},
                                 {v1.z, v1.w, v2.x}, {v2.y, v2.z, v2.w}};
#pragma unroll
                for (int j = 0; j < 4; j++)
#pragma unroll
                    for (int c = 0; c < 3; c++)
                        hm[c][j] = cw[c * 3] * g[j][0] + cw[c * 3 + 1] * g[j][1] + cw[c * 3 + 2] * g[j][2];
            }
            float he[3] = {0.f, 0.f, 0.f};
            if (yok && is_e && ex_ok) {
                const float* pe = xb + (size_t)(yin * W_IMG + ex) * 3;
                float g0 = pe[0], g1 = pe[1], g2 = pe[2];
#pragma unroll
                for (int c = 0; c < 3; c++)
                    he[c] = cw[c * 3] * g0 + cw[c * 3 + 1] * g1 + cw[c * 3 + 2] * g2;
            }
            float hl[3], hr[3];
#pragma unroll
            for (int c = 0; c < 3; c++) {
                hl[c] = __shfl_up_sync(0xffffffffu, hm[c][3], 1);
                hr[c] = __shfl_down_sync(0xffffffffu, hm[c][0], 1);
                if (lane == 0) hl[c] = he[c];
                if (lane == 31) hr[c] = he[c];
            }
#pragma unroll
            for (int c = 0; c < 3; c++)
#pragma unroll
                for (int j = 0; j < 4; j++) {
                    float L = j ? hm[c][j - 1] : hl[c];
                    float M_ = hm[c][j];
                    float R = (j < 3) ? hm[c][j + 1] : hr[c];
                    a0[c][j] += dw[c * 9 + 6] * L + dw[c * 9 + 7] * M_ + dw[c * 9 + 8] * R;
                    a1[c][j] += dw[c * 9 + 3] * L + dw[c * 9 + 4] * M_ + dw[c * 9 + 5] * R;
                    a2[c][j] += dw[c * 9 + 0] * L + dw[c * 9 + 1] * M_ + dw[c * 9 + 2] * R;
                }
            if (iy >= 2) {
                const int r = iy - 2;
#pragma unroll
                for (int c = 0; c < 3; c++)
#pragma unroll
                    for (int j = 0; j < 4; j++) {
                        float v = a0[c][j];
                        kout[c][r][j] = v;
                        p[3 + c] += v * v;
                    }
            }
#pragma unroll
            for (int c = 0; c < 3; c++)
#pragma unroll
                for (int j = 0; j < 4; j++) {
                    a0[c][j] = a1[c][j];
                    a1[c][j] = a2[c][j];
                    a2[c][j] = 0.f;
                }
        }
    }

    // ================= Q path (input fhigh, planar) =================
    {
        float cw[9], dw[27];
#pragma unroll
        for (int i = 0; i < 9; i++) cw[i] = qC[i];
#pragma unroll
        for (int i = 0; i < 27; i++) dw[i] = qD[i];

        float a0[3][4], a1[3][4], a2[3][4];
#pragma unroll
        for (int c = 0; c < 3; c++)
#pragma unroll
            for (int j = 0; j < 4; j++) { a0[c][j] = a1[c][j] = a2[c][j] = 0.f; }

#pragma unroll
        for (int iy = 0; iy < 6; iy++) {
            const int yin = y0 + iy - 1;
            const bool yok = (unsigned)yin < (unsigned)W_IMG;

            float hm[3][4];
#pragma unroll
            for (int c = 0; c < 3; c++)
#pragma unroll
                for (int j = 0; j < 4; j++) hm[c][j] = 0.f;

            if (yok) {
                const size_t o = (size_t)yin * W_IMG + px0;
                float4 f0 = *(const float4*)(fb + o);
                float4 f1 = *(const float4*)(fb + o + N_PIX);
                float4 f2 = *(const float4*)(fb + o + 2 * N_PIX);
                float g[4][3] = {{f0.x, f1.x, f2.x}, {f0.y, f1.y, f2.y},
                                 {f0.z, f1.z, f2.z}, {f0.w, f1.w, f2.w}};
#pragma unroll
                for (int j = 0; j < 4; j++)
#pragma unroll
                    for (int c = 0; c < 3; c++)
                        hm[c][j] = cw[c * 3] * g[j][0] + cw[c * 3 + 1] * g[j][1] + cw[c * 3 + 2] * g[j][2];
            }
            float he[3] = {0.f, 0.f, 0.f};
            if (yok && is_e && ex_ok) {
                const size_t o = (size_t)yin * W_IMG + ex;
                float g0 = fb[o], g1 = fb[o + N_PIX], g2 = fb[o + 2 * N_PIX];
#pragma unroll
                for (int c = 0; c < 3; c++)
                    he[c] = cw[c * 3] * g0 + cw[c * 3 + 1] * g1 + cw[c * 3 + 2] * g2;
            }
            float hl[3], hr[3];
#pragma unroll
            for (int c = 0; c < 3; c++) {
                hl[c] = __shfl_up_sync(0xffffffffu, hm[c][3], 1);
                hr[c] = __shfl_down_sync(0xffffffffu, hm[c][0], 1);
                if (lane == 0) hl[c] = he[c];
                if (lane == 31) hr[c] = he[c];
            }
#pragma unroll
            for (int c = 0; c < 3; c++)
#pragma unroll
                for (int j = 0; j < 4; j++) {
                    float L = j ? hm[c][j - 1] : hl[c];
                    float M_ = hm[c][j];
                    float R = (j < 3) ? hm[c][j + 1] : hr[c];
                    a0[c][j] += dw[c * 9 + 6] * L + dw[c * 9 + 7] * M_ + dw[c * 9 + 8] * R;
                    a1[c][j] += dw[c * 9 + 3] * L + dw[c * 9 + 4] * M_ + dw[c * 9 + 5] * R;
                    a2[c][j] += dw[c * 9 + 0] * L + dw[c * 9 + 1] * M_ + dw[c * 9 + 2] * R;
                }
            if (iy >= 2) {
                const int r = iy - 2;
#pragma unroll
                for (int c = 0; c < 3; c++)
#pragma unroll
                    for (int j = 0; j < 4; j++) {
                        float q = a0[c][j];
                        p[c] += q * q;
#pragma unroll
                        for (int d = 0; d < 3; d++)
                            p[6 + c * 3 + d] += q * kout[d][r][j];
                    }
            }
#pragma unroll
            for (int c = 0; c < 3; c++)
#pragma unroll
                for (int j = 0; j < 4; j++) {
                    a0[c][j] = a1[c][j];
                    a1[c][j] = a2[c][j];
                    a2[c][j] = 0.f;
                }
        }
    }

    // reduce -> per-block partial (no atomics, no pre-zeroing needed)
#pragma unroll
    for (int i = 0; i < 15; i++)
#pragma unroll
        for (int o = 16; o; o >>= 1)
            p[i] += __shfl_down_sync(0xffffffffu, p[i], o);
    if (lane == 0) {
#pragma unroll
        for (int i = 0; i < 15; i++) red[warp][i] = p[i];
    }
    __syncthreads();
    if (tid < 15) {
        float t = 0.f;
#pragma unroll
        for (int w2 = 0; w2 < NTH / 32; w2++) t += red[w2][tid];
        g_part[b][blockIdx.y * 8 + blockIdx.x][tid] = t;
    }
}

// ---------------------------------------------------------------------------
// k_out: prologue reduces 256 partials -> stats -> M; body = 4x8 patch
// k-conv + 3x3 map (proven R7 version).
// ---------------------------------------------------------------------------
__global__ __launch_bounds__(NTH) void k_out(const float* __restrict__ x,
                                             const float* __restrict__ kC,
                                             const float* __restrict__ kD,
                                             const float* __restrict__ proj_w,
                                             const float* __restrict__ proj_b,
                                             const float* __restrict__ temp,
                                             float* __restrict__ out) {
    __shared__ float sM[9];
    __shared__ float sred[NTH / 32][15];
    __shared__ float sstat[15];

    const int tid = threadIdx.x;
    const int b = blockIdx.z;
    const int warp = tid >> 5, lane = tid & 31;

    // --- prologue: reduce 256 partials x 15, then compute M ---
    {
        float p[15];
        const float4* row = (const float4*)g_part[b][tid];
        float4 v0 = row[0], v1 = row[1], v2 = row[2], v3 = row[3];
        p[0] = v0.x;  p[1] = v0.y;  p[2] = v0.z;  p[3] = v0.w;
        p[4] = v1.x;  p[5] = v1.y;  p[6] = v1.z;  p[7] = v1.w;
        p[8] = v2.x;  p[9] = v2.y;  p[10] = v2.z; p[11] = v2.w;
        p[12] = v3.x; p[13] = v3.y; p[14] = v3.z;
#pragma unroll
        for (int i = 0; i < 15; i++)
#pragma unroll
            for (int o = 16; o; o >>= 1)
                p[i] += __shfl_down_sync(0xffffffffu, p[i], o);
        if (lane == 0) {
#pragma unroll
            for (int i = 0; i < 15; i++) sred[warp][i] = p[i];
        }
        __syncthreads();
        if (tid < 15) {
            float t = 0.f;
#pragma unroll
            for (int w2 = 0; w2 < NTH / 32; w2++) t += sred[w2][tid];
            sstat[tid] = t;
        }
        __syncthreads();
        if (tid == 0) {
            float T = temp[0];
            float nq[3], nk[3];
#pragma unroll
            for (int c = 0; c < 3; c++) {
                nq[c] = fmaxf(sqrtf(sstat[c]), 1e-12f);
                nk[c] = fmaxf(sqrtf(sstat[3 + c]), 1e-12f);
            }
            float a[3][3];
#pragma unroll
            for (int c = 0; c < 3; c++)
#pragma unroll
                for (int d = 0; d < 3; d++)
                    a[c][d] = sstat[6 + c * 3 + d] / (nq[c] * nk[d]) * T;
#pragma unroll
            for (int c = 0; c < 3; c++) {
                float mx = fmaxf(a[c][0], fmaxf(a[c][1], a[c][2]));
                float e0 = expf(a[c][0] - mx);
                float e1 = expf(a[c][1] - mx);
                float e2 = expf(a[c][2] - mx);
                float inv = 1.f / (e0 + e1 + e2);
                a[c][0] = e0 * inv; a[c][1] = e1 * inv; a[c][2] = e2 * inv;
            }
#pragma unroll
            for (int co = 0; co < 3; co++)
#pragma unroll
                for (int d = 0; d < 3; d++) {
                    float mm = 0.f;
#pragma unroll
                    for (int c = 0; c < 3; c++) mm += proj_w[co * 3 + c] * a[c][d];
                    sM[co * 3 + d] = mm;
                }
        }
        __syncthreads();
    }

    const int wx0 = blockIdx.x * 128;
    const int px0 = wx0 + lane * 4;
    const int y0 = blockIdx.y * 64 + warp * 8;

    const float* __restrict__ xb = x + (size_t)b * 3 * N_PIX;

    const bool is_e = (lane == 0) | (lane == 31);
    const int ex = (lane == 0) ? wx0 - 1 : wx0 + 128;
    const bool ex_ok = (unsigned)ex < (unsigned)W_IMG;

    float cw[9], dw[27];
#pragma unroll
    for (int i = 0; i < 9; i++) cw[i] = kC[i];
#pragma unroll
    for (int i = 0; i < 27; i++) dw[i] = kD[i];

    float m[9];
#pragma unroll
    for (int i = 0; i < 9; i++) m[i] = sM[i];
    const float b0 = proj_b[0], b1 = proj_b[1], b2 = proj_b[2];

    float a0[3][4], a1[3][4], a2[3][4];
#pragma unroll
    for (int c = 0; c < 3; c++)
#pragma unroll
        for (int j = 0; j < 4; j++) { a0[c][j] = a1[c][j] = a2[c][j] = 0.f; }

#pragma unroll
    for (int iy = 0; iy < 10; iy++) {
        const int yin = y0 + iy - 1;
        const bool yok = (unsigned)yin < (unsigned)W_IMG;

        float hm[3][4];
#pragma unroll
        for (int c = 0; c < 3; c++)
#pragma unroll
            for (int j = 0; j < 4; j++) hm[c][j] = 0.f;

        if (yok) {
            const float4* p4 = (const float4*)(xb + (size_t)(yin * W_IMG + px0) * 3);
            float4 v0 = p4[0], v1 = p4[1], v2 = p4[2];
            float g[4][3] = {{v0.x, v0.y, v0.z}, {v0.w, v1.x, v1.y},
                             {v1.z, v1.w, v2.x}, {v2.y, v2.z, v2.w}};
#pragma unroll
            for (int j = 0; j < 4; j++)
#pragma unroll
                for (int c = 0; c < 3; c++)
                    hm[c][j] = cw[c * 3] * g[j][0] + cw[c * 3 + 1] * g[j][1] + cw[c * 3 + 2] * g[j][2];
        }
        float he[3] = {0.f, 0.f, 0.f};
        if (yok && is_e && ex_ok) {
            const float* pe = xb + (size_t)(yin * W_IMG + ex) * 3;
            float g0 = pe[0], g1 = pe[1], g2 = pe[2];
#pragma unroll
            for (int c = 0; c < 3; c++)
                he[c] = cw[c * 3] * g0 + cw[c * 3 + 1] * g1 + cw[c * 3 + 2] * g2;
        }
        float hl[3], hr[3];
#pragma unroll
        for (int c = 0; c < 3; c++) {
            hl[c] = __shfl_up_sync(0xffffffffu, hm[c][3], 1);
            hr[c] = __shfl_down_sync(0xffffffffu, hm[c][0], 1);
            if (lane == 0) hl[c] = he[c];
            if (lane == 31) hr[c] = he[c];
        }
#pragma unroll
        for (int c = 0; c < 3; c++)
#pragma unroll
            for (int j = 0; j < 4; j++) {
                float L = j ? hm[c][j - 1] : hl[c];
                float M_ = hm[c][j];
                float R = (j < 3) ? hm[c][j + 1] : hr[c];
                a0[c][j] += dw[c * 9 + 6] * L + dw[c * 9 + 7] * M_ + dw[c * 9 + 8] * R;
                a1[c][j] += dw[c * 9 + 3] * L + dw[c * 9 + 4] * M_ + dw[c * 9 + 5] * R;
                a2[c][j] += dw[c * 9 + 0] * L + dw[c * 9 + 1] * M_ + dw[c * 9 + 2] * R;
            }
        if (iy >= 2) {
            const int yout = y0 + iy - 2;
            float o[12];
#pragma unroll
            for (int j = 0; j < 4; j++) {
                float k0 = a0[0][j], k1 = a0[1][j], k2 = a0[2][j];
                o[j * 3 + 0] = m[0] * k0 + m[1] * k1 + m[2] * k2 + b0;
                o[j * 3 + 1] = m[3] * k0 + m[4] * k1 + m[5] * k2 + b1;
                o[j * 3 + 2] = m[6] * k0 + m[7] * k1 + m[8] * k2 + b2;
            }
            float4* q4 = (float4*)(out + ((size_t)b * N_PIX + (size_t)yout * W_IMG + px0) * 3);
            q4[0] = make_float4(o[0], o[1], o[2], o[3]);
            q4[1] = make_float4(o[4], o[5], o[6], o[7]);
            q4[2] = make_float4(o[8], o[9], o[10], o[11]);
        }
#pragma unroll
        for (int c = 0; c < 3; c++)
#pragma unroll
            for (int j = 0; j < 4; j++) {
                a0[c][j] = a1[c][j];
                a1[c][j] = a2[c][j];
                a2[c][j] = 0.f;
            }
    }
}

extern "C" void kernel_launch(void* const* d_in, const int* in_sizes, int n_in,
                              void* d_out, int out_size) {
    const float* x     = (const float*)d_in[0];
    const float* fhigh = (const float*)d_in[1];
    const float* qCw   = (const float*)d_in[2];
    const float* qdw   = (const float*)d_in[3];
    const float* kCw   = (const float*)d_in[4];
    const float* kdw   = (const float*)d_in[5];
    const float* projw = (const float*)d_in[6];
    const float* projb = (const float*)d_in[7];
    const float* temp  = (const float*)d_in[8];
    float* out = (float*)d_out;

    int B = in_sizes[0] / (N_PIX * 3);
    if (B > MAXB) B = MAXB;

    dim3 gridS(W_IMG / 128, W_IMG / 32, B);   // 8 x 32 = 256 blocks per batch
    k_stats<<<gridS, NTH>>>(x, fhigh, qCw, qdw, kCw, kdw);
    dim3 gridO(W_IMG / 128, W_IMG / 64, B);
    k_out<<<gridO, NTH>>>(x, kCw, kdw, projw, projb, temp, out);
}